// round 14
// baseline (speedup 1.0000x reference)
#include <cuda_runtime.h>
#include <cuda_fp16.h>
#include <cstdint>

// ---------------------------------------------------------------------------
// Problem constants
// ---------------------------------------------------------------------------
#define BB    2
#define CIN   256
#define HH    56
#define WW    56
#define OUTC  256
#define KK    7
#define PADV  3
#define GRP   8
#define CG    32
#define NQ    (HH*WW)     // 3136 = 49*64

#define KT    32          // fp32 channels per k-tile
#define STR2  20          // A SMEM u32 stride per row (16 words + 4 pad)
#define BSTRB 144         // B SMEM byte stride per k-row (128B data + 16 pad)
#define CSTR  132         // epilogue transpose stride

#define TPB   196
#define TOT_TILES (3*TPB) // 588

#define W_ITEMS (3*256*128)        // weight u32 words
#define X_ITEMS (1024*784)         // fm float4 units
#define PREP_T  (W_ITEMS + X_ITEMS)

// ---------------------------------------------------------------------------
// helpers (portable sm_80+ PTX)
// ---------------------------------------------------------------------------
__device__ __forceinline__ void mma16(float* c, const uint32_t* a, const uint32_t* b) {
    asm volatile("mma.sync.aligned.m16n8k16.row.col.f32.bf16.bf16.f32 "
        "{%0,%1,%2,%3}, {%4,%5,%6,%7}, {%8,%9}, {%0,%1,%2,%3};"
        : "+f"(c[0]), "+f"(c[1]), "+f"(c[2]), "+f"(c[3])
        : "r"(a[0]), "r"(a[1]), "r"(a[2]), "r"(a[3]), "r"(b[0]), "r"(b[1]));
}
__device__ __forceinline__ uint32_t pk_bf2(float hi_f, float lo_f) {
    uint32_t r;
    asm("cvt.rn.bf16x2.f32 %0, %1, %2;" : "=r"(r) : "f"(hi_f), "f"(lo_f));
    return r;
}
__device__ __forceinline__ float bf_lo_f(uint32_t w) { return __uint_as_float(w << 16); }
__device__ __forceinline__ float bf_hi_f(uint32_t w) { return __uint_as_float(w & 0xFFFF0000u); }

__device__ __forceinline__ uint32_t smem_u32(const void* p) {
    return (uint32_t)__cvta_generic_to_shared(p);
}
__device__ __forceinline__ void cpa16(uint32_t dst, const void* src) {
    asm volatile("cp.async.ca.shared.global [%0], [%1], 16;" :: "r"(dst), "l"(src));
}
#define CPA_COMMIT() asm volatile("cp.async.commit_group;" ::: "memory")
#define CPA_WAIT0()  asm volatile("cp.async.wait_group 0;"  ::: "memory")
#define CPA_WAIT1()  asm volatile("cp.async.wait_group 1;"  ::: "memory")

// ldmatrix: A fragment (m16k16) from [row][k-word] layout, byte-base abase
__device__ __forceinline__ void ldsmA(uint32_t* f, uint32_t abase, int mb, int kw0, int l) {
    uint32_t addr = abase + (uint32_t)(((mb + (l & 15)) * STR2 + kw0 + ((l >> 2) & 4)) * 4);
    asm volatile("ldmatrix.sync.aligned.m8n8.x4.shared.b16 {%0,%1,%2,%3}, [%4];"
        : "=r"(f[0]), "=r"(f[1]), "=r"(f[2]), "=r"(f[3]) : "r"(addr));
}
// ldmatrix trans: B fragment (n8k16) from k-major [k][n bf16] layout
__device__ __forceinline__ void ldsmBt(uint32_t* f, uint32_t bbase, int nb, int k0, int l) {
    uint32_t addr = bbase + (uint32_t)((k0 + (l & 15)) * BSTRB + nb * 2);
    asm volatile("ldmatrix.sync.aligned.m8n8.x2.trans.shared.b16 {%0,%1}, [%2];"
        : "=r"(f[0]), "=r"(f[1]) : "r"(addr));
}

// ---------------------------------------------------------------------------
// Scratch (device globals)
// ---------------------------------------------------------------------------
__device__ float g_q[BB * NQ * OUTC];
__device__ float g_k[BB * NQ * OUTC];
__device__ float g_v[BB * NQ * OUTC];
__device__ uint32_t g_wh[3 * 256 * 128];
__device__ uint32_t g_wl[3 * 256 * 128];
__device__ uint32_t g_xh[1024 * 1568];
__device__ uint32_t g_xl[1024 * 1568];

// ---------------------------------------------------------------------------
// 0) Prep: weights AND fm -> bf16 hi/lo (element-wise, coalesced)
// ---------------------------------------------------------------------------
__global__ void prep_all(const float* __restrict__ fm, const float* __restrict__ wq,
                         const float* __restrict__ wk, const float* __restrict__ wv) {
    int idx = blockIdx.x * blockDim.x + threadIdx.x;
    if (idx < W_ITEMS) {
        int type = idx / (256 * 128);
        int rem  = idx % (256 * 128);
        const float* W = (type == 0) ? wq : (type == 1) ? wk : wv;
        float2 v = *(const float2*)&W[(size_t)rem * 2];
        uint32_t wh = pk_bf2(v.y, v.x);
        float l0 = v.x - bf_lo_f(wh), l1 = v.y - bf_hi_f(wh);
        g_wh[idx] = wh;
        g_wl[idx] = pk_bf2(l1, l0);
    } else {
        int j = idx - W_ITEMS;
        if (j >= X_ITEMS) return;
        int row = j / 784, n4 = j % 784;
        float4 v = *(const float4*)&fm[(size_t)row * NQ + n4 * 4];
        uint32_t h0 = pk_bf2(v.y, v.x);
        uint32_t h1 = pk_bf2(v.w, v.z);
        float l0 = v.x - bf_lo_f(h0), l1 = v.y - bf_hi_f(h0);
        float l2 = v.z - bf_lo_f(h1), l3 = v.w - bf_hi_f(h1);
        size_t o = (size_t)row * 1568 + n4 * 2;
        *(uint2*)&g_xh[o] = make_uint2(h0, h1);
        *(uint2*)&g_xl[o] = make_uint2(pk_bf2(l1, l0), pk_bf2(l3, l2));
    }
}

// ---------------------------------------------------------------------------
// Fused GEMM (round-11 config): 3xBF16 m16n8k16, all-cp.async, ldmatrix,
// 3-stage pipeline. Tile 128(o) x 64(n); 8 warps 4x2; warp 32x32.
// ---------------------------------------------------------------------------
#define A_W     (128 * STR2)
#define AH_OFF  0
#define AL_OFF  (A_W * 4)
#define BH_OFF  (2 * A_W * 4)
#define BL_OFF  (BH_OFF + 32 * BSTRB)
#define STAGE_B (BL_OFF + 32 * BSTRB)
#define NSTG    3
#define G_SMEMB (NSTG * STAGE_B)

__global__ __launch_bounds__(256, 2) void gemm_all(void) {
    extern __shared__ uint32_t smu[];
    const uint32_t sbase = smem_u32(smu);

    const int t  = threadIdx.x;
    const int id = blockIdx.x;

    const int type  = id / TPB;
    const int local = id % TPB;
    const int ni_t = local % 49;
    const int rest = local / 49;
    const int o0 = (rest & 1) * 128;
    const int b  = rest >> 1;
    const int n0 = ni_t * 64;

    float* D = ((type == 0) ? g_q : (type == 1) ? g_k : g_v) + (size_t)b * NQ * OUTC;
    const uint32_t* WHrow = g_wh + ((size_t)type * 256 + o0) * 128;
    const uint32_t* WLrow = g_wl + ((size_t)type * 256 + o0) * 128;
    const int srcrow0 = b * 512 + (type == 0 ? 256 : 0);

    const int wid = t >> 5, l = t & 31;
    const int m0w = (wid & 3) * 32;
    const int n0w = (wid >> 2) * 32;
    const int am = t >> 2, af = t & 3;
    const int brow = t >> 3, bchunk = t & 7;

    float c[2][4][4];
#pragma unroll
    for (int mi = 0; mi < 2; mi++)
#pragma unroll
        for (int ni = 0; ni < 4; ni++)
#pragma unroll
            for (int e = 0; e < 4; e++) c[mi][ni][e] = 0.f;

#define STAGE_LOAD(stb, ktile)                                                     \
    {                                                                              \
        int kw = (ktile) * 16;                                                     \
        _Pragma("unroll")                                                          \
        for (int i = 0; i < 2; i++) {                                              \
            int m = am + i * 64;                                                   \
            uint32_t doff = (uint32_t)((m * STR2 + af * 4) * 4);                   \
            cpa16((stb) + AH_OFF + doff, WHrow + (size_t)m * 128 + kw + af * 4);   \
            cpa16((stb) + AL_OFF + doff, WLrow + (size_t)m * 128 + kw + af * 4);   \
        }                                                                          \
        {                                                                          \
            size_t srcoff = ((size_t)(srcrow0 + (ktile) * KT + brow) * NQ          \
                             + n0 + bchunk * 8) * 2;                               \
            uint32_t doff = (uint32_t)(brow * BSTRB + bchunk * 16);                \
            cpa16((stb) + BH_OFF + doff, (const char*)g_xh + srcoff);              \
            cpa16((stb) + BL_OFF + doff, (const char*)g_xl + srcoff);              \
        }                                                                          \
        CPA_COMMIT();                                                              \
    }

    STAGE_LOAD(sbase, 0);
    STAGE_LOAD(sbase + STAGE_B, 1);
    CPA_WAIT1();
    __syncthreads();

#pragma unroll 1
    for (int kt = 0; kt < CIN / KT; kt++) {
        const int s = kt % NSTG;
        const uint32_t stb = sbase + (uint32_t)(s * STAGE_B);
        const uint32_t aH = stb + AH_OFF;
        const uint32_t aL = stb + AL_OFF;
        const uint32_t bH = stb + BH_OFF;
        const uint32_t bL = stb + BL_OFF;

        if (kt + 2 < CIN / KT) {
            STAGE_LOAD(sbase + (uint32_t)(((kt + 2) % NSTG) * STAGE_B), kt + 2);
        }

#pragma unroll
        for (int ks = 0; ks < 2; ks++) {
            const int kw0 = ks * 8;
            const int k0  = ks * 16;
            uint32_t ah0[4], ah1[4], al0[4], al1[4];
            ldsmA(ah0, aH, m0w,      kw0, l);
            ldsmA(ah1, aH, m0w + 16, kw0, l);
            ldsmA(al0, aL, m0w,      kw0, l);
            ldsmA(al1, aL, m0w + 16, kw0, l);
#pragma unroll
            for (int ni = 0; ni < 4; ni++) {
                uint32_t bh[2], bl[2];
                ldsmBt(bh, bH, n0w + ni * 8, k0, l);
                ldsmBt(bl, bL, n0w + ni * 8, k0, l);
                mma16(c[0][ni], ah0, bh);
                mma16(c[0][ni], ah0, bl);
                mma16(c[0][ni], al0, bh);
                mma16(c[1][ni], ah1, bh);
                mma16(c[1][ni], ah1, bl);
                mma16(c[1][ni], al1, bh);
            }
        }

        if (kt + 2 < CIN / KT) { CPA_WAIT1(); } else { CPA_WAIT0(); }
        __syncthreads();
    }

    const int r = l >> 2, q = l & 3;
    float* Ct = (float*)smu;
#pragma unroll
    for (int mi = 0; mi < 2; mi++)
#pragma unroll
        for (int ni = 0; ni < 4; ni++) {
            int m = m0w + mi * 16 + r;
            int n = n0w + ni * 8 + q * 2;
            Ct[(n)     * CSTR + m]     = c[mi][ni][0];
            Ct[(n + 1) * CSTR + m]     = c[mi][ni][1];
            Ct[(n)     * CSTR + m + 8] = c[mi][ni][2];
            Ct[(n + 1) * CSTR + m + 8] = c[mi][ni][3];
        }
    __syncthreads();
#pragma unroll
    for (int i = 0; i < 8; i++) {
        int id2 = t + i * 256;
        int n = id2 >> 5, f = id2 & 31;
        float4 v = *(float4*)&Ct[n * CSTR + f * 4];
        *(float4*)&D[(size_t)(n0 + n) * OUTC + o0 + f * 4] = v;
    }
}

// ---------------------------------------------------------------------------
// Attention: 8x8 tiles, 128 thr, 2 threads/pixel; K fp32 + V fp16 in SMEM.
// SMEM 38.7 KB -> 5 blocks/SM (launch_bounds 128,5); pass-2 LDS bytes halved.
// ---------------------------------------------------------------------------
#define TPIX   14
#define NPIX   (TPIX*TPIX)
#define SSTR   197
// ks: 8*SSTR float4 (25216 B) ; vsh: 8*SSTR uint2 (12608 B) ; bias 896 B
#define ATTN_SMEM (8 * SSTR * 16 + 8 * SSTR * 8 + CG * KK * 4)   // 38720 B

__global__ __launch_bounds__(128, 5) void attn_kernel(const float* __restrict__ relh,
                                                      const float* __restrict__ relw,
                                                      float* __restrict__ out) {
    extern __shared__ float4 smbuf[];
    float4* ks   = smbuf;                              // [8][SSTR] fp32x4
    uint2*  vsh  = (uint2*)(smbuf + 8 * SSTR);         // [8][SSTR] half x4
    float*  bias = (float*)((char*)smbuf + 8 * SSTR * 16 + 8 * SSTR * 8);

    const int b    = blockIdx.z;
    const int g    = blockIdx.y;
    const int tile = blockIdx.x;
    const int ty0  = (tile / 7) * 8;
    const int tx0  = (tile % 7) * 8;
    const int t    = threadIdx.x;
    const int p    = t >> 1;
    const int half = t & 1;

    const float* rel = (g < 4) ? (relh + (size_t)g * CG * KK)
                               : (relw + (size_t)(g - 4) * CG * KK);
    for (int i = t; i < CG * KK; i += 128) bias[i] = rel[i];

    for (int idx = t; idx < NPIX * 8; idx += 128) {
        int c4 = idx & 7;
        int pp = idx >> 3;
        int py = pp / TPIX, px = pp - py * TPIX;
        int yy = ty0 + py - PADV, xx = tx0 + px - PADV;
        float4 kv = make_float4(0.f, 0.f, 0.f, 0.f);
        float4 vv = make_float4(0.f, 0.f, 0.f, 0.f);
        if (yy >= 0 && yy < HH && xx >= 0 && xx < WW) {
            size_t gbase = ((size_t)b * NQ + yy * WW + xx) * OUTC + g * CG;
            kv = *((const float4*)&g_k[gbase] + c4);
            vv = *((const float4*)&g_v[gbase] + c4);
        }
        ks[c4 * SSTR + pp] = kv;
        __half2 v01 = __floats2half2_rn(vv.x, vv.y);
        __half2 v23 = __floats2half2_rn(vv.z, vv.w);
        uint2 packed;
        packed.x = *(uint32_t*)&v01;
        packed.y = *(uint32_t*)&v23;
        vsh[c4 * SSTR + pp] = packed;
    }
    __syncthreads();

    const int lty = p >> 3, ltx = p & 7;
    const int h = ty0 + lty, w = tx0 + ltx;
    const int pbase = lty * TPIX + ltx;
    const int c4b = half * 4;

    float qf[16];
    {
        const float4* qp = (const float4*)&g_q[((size_t)b * NQ + h * WW + w) * OUTC + g * CG];
#pragma unroll
        for (int c4 = 0; c4 < 4; c4++) {
            float4 v = qp[c4b + c4];
            qf[c4 * 4 + 0] = v.x; qf[c4 * 4 + 1] = v.y;
            qf[c4 * 4 + 2] = v.z; qf[c4 * 4 + 3] = v.w;
        }
    }

    float db[KK];
#pragma unroll
    for (int i = 0; i < KK; i++) {
        float s = 0.f;
#pragma unroll
        for (int c = 0; c < 16; c++) s += qf[c] * bias[(half * 16 + c) * KK + i];
        db[i] = s;
    }
#pragma unroll
    for (int i = 0; i < KK; i++) db[i] += __shfl_xor_sync(0xffffffffu, db[i], 1);

    float lg[KK * KK];
#pragma unroll
    for (int n = 0; n < KK * KK; n++) {
        const int i = n / KK, j = n % KK;
        const int pp = pbase + i * TPIX + j;
        float s = 0.f;
#pragma unroll
        for (int c4 = 0; c4 < 4; c4++) {
            float4 kv = ks[(c4b + c4) * SSTR + pp];
            s += qf[c4 * 4 + 0] * kv.x + qf[c4 * 4 + 1] * kv.y
               + qf[c4 * 4 + 2] * kv.z + qf[c4 * 4 + 3] * kv.w;
        }
        lg[n] = s;
    }
#pragma unroll
    for (int n = 0; n < KK * KK; n++)
        lg[n] += __shfl_xor_sync(0xffffffffu, lg[n], 1);
#pragma unroll
    for (int n = 0; n < KK * KK; n++)
        lg[n] += (g < 4) ? db[n / KK] : db[n % KK];

    float mx = lg[0];
#pragma unroll
    for (int n = 1; n < KK * KK; n++) mx = fmaxf(mx, lg[n]);
    float sum = 0.f;
#pragma unroll
    for (int n = 0; n < KK * KK; n++) { lg[n] = __expf(lg[n] - mx); sum += lg[n]; }
    float inv = 1.f / sum;
#pragma unroll
    for (int n = 0; n < KK * KK; n++) lg[n] *= inv;

#pragma unroll
    for (int c4 = 0; c4 < 4; c4++) {
        float4 acc = make_float4(0.f, 0.f, 0.f, 0.f);
#pragma unroll
        for (int n = 0; n < KK * KK; n++) {
            const int pp = pbase + (n / KK) * TPIX + (n % KK);
            uint2 raw = vsh[(c4b + c4) * SSTR + pp];
            float2 f01 = __half22float2(*(__half2*)&raw.x);
            float2 f23 = __half22float2(*(__half2*)&raw.y);
            acc.x += lg[n] * f01.x;
            acc.y += lg[n] * f01.y;
            acc.z += lg[n] * f23.x;
            acc.w += lg[n] * f23.y;
        }
        size_t base = ((size_t)(b * OUTC + g * CG + (c4b + c4) * 4)) * NQ + h * WW + w;
        out[base]          = acc.x;
        out[base + NQ]     = acc.y;
        out[base + 2 * NQ] = acc.z;
        out[base + 3 * NQ] = acc.w;
    }
}

// ---------------------------------------------------------------------------
// Launch
// ---------------------------------------------------------------------------
extern "C" void kernel_launch(void* const* d_in, const int* in_sizes, int n_in,
                              void* d_out, int out_size) {
    const float* fm = (const float*)d_in[0];
    const float* wq = (const float*)d_in[1];
    const float* wk = (const float*)d_in[2];
    const float* wv = (const float*)d_in[3];
    const float* rh = (const float*)d_in[4];
    const float* rw = (const float*)d_in[5];
    float* out = (float*)d_out;

    cudaFuncSetAttribute(attn_kernel, cudaFuncAttributeMaxDynamicSharedMemorySize, ATTN_SMEM);
    cudaFuncSetAttribute(gemm_all,    cudaFuncAttributeMaxDynamicSharedMemorySize, G_SMEMB);

    prep_all<<<(PREP_T + 255) / 256, 256>>>(fm, wq, wk, wv);
    gemm_all<<<TOT_TILES, 256, G_SMEMB>>>();
    attn_kernel<<<dim3(49, GRP, BB), 128, ATTN_SMEM>>>(rh, rw, out);
}

// round 15
// speedup vs baseline: 1.0747x; 1.0747x over previous
#include <cuda_runtime.h>
#include <cstdint>

// ---------------------------------------------------------------------------
// Problem constants
// ---------------------------------------------------------------------------
#define BB    2
#define CIN   256
#define HH    56
#define WW    56
#define OUTC  256
#define KK    7
#define PADV  3
#define GRP   8
#define CG    32
#define NQ    (HH*WW)     // 3136 = 49*64

#define KT    32          // fp32 channels per k-tile
#define STR2  20          // A SMEM u32 stride per row (16 words + 4 pad)
#define BSTRB 144         // B SMEM byte stride per k-row (128B data + 16 pad)
#define CSTR  132         // epilogue transpose stride

#define TPB   196
#define TOT_TILES (3*TPB) // 588

#define W_ITEMS (3*256*128)        // weight u32 words
#define X_ITEMS (1024*784)         // fm float4 units
#define X_HALF  (X_ITEMS/2)        // 401408
#define PREP_T  (W_ITEMS + X_HALF) // each fm thread handles 2 items (MLP=2)

// ---------------------------------------------------------------------------
// helpers (portable sm_80+ PTX)
// ---------------------------------------------------------------------------
__device__ __forceinline__ void mma16(float* c, const uint32_t* a, const uint32_t* b) {
    asm volatile("mma.sync.aligned.m16n8k16.row.col.f32.bf16.bf16.f32 "
        "{%0,%1,%2,%3}, {%4,%5,%6,%7}, {%8,%9}, {%0,%1,%2,%3};"
        : "+f"(c[0]), "+f"(c[1]), "+f"(c[2]), "+f"(c[3])
        : "r"(a[0]), "r"(a[1]), "r"(a[2]), "r"(a[3]), "r"(b[0]), "r"(b[1]));
}
__device__ __forceinline__ uint32_t pk_bf2(float hi_f, float lo_f) {
    uint32_t r;
    asm("cvt.rn.bf16x2.f32 %0, %1, %2;" : "=r"(r) : "f"(hi_f), "f"(lo_f));
    return r;
}
__device__ __forceinline__ float bf_lo_f(uint32_t w) { return __uint_as_float(w << 16); }
__device__ __forceinline__ float bf_hi_f(uint32_t w) { return __uint_as_float(w & 0xFFFF0000u); }

__device__ __forceinline__ uint32_t smem_u32(const void* p) {
    return (uint32_t)__cvta_generic_to_shared(p);
}
__device__ __forceinline__ void cpa16(uint32_t dst, const void* src) {
    asm volatile("cp.async.ca.shared.global [%0], [%1], 16;" :: "r"(dst), "l"(src));
}
#define CPA_COMMIT() asm volatile("cp.async.commit_group;" ::: "memory")
#define CPA_WAIT0()  asm volatile("cp.async.wait_group 0;"  ::: "memory")
#define CPA_WAIT1()  asm volatile("cp.async.wait_group 1;"  ::: "memory")

// ldmatrix: A fragment (m16k16) from [row][k-word] layout, byte-base abase
__device__ __forceinline__ void ldsmA(uint32_t* f, uint32_t abase, int mb, int kw0, int l) {
    uint32_t addr = abase + (uint32_t)(((mb + (l & 15)) * STR2 + kw0 + ((l >> 2) & 4)) * 4);
    asm volatile("ldmatrix.sync.aligned.m8n8.x4.shared.b16 {%0,%1,%2,%3}, [%4];"
        : "=r"(f[0]), "=r"(f[1]), "=r"(f[2]), "=r"(f[3]) : "r"(addr));
}
// ldmatrix trans: B fragment (n8k16) from k-major [k][n bf16] layout
__device__ __forceinline__ void ldsmBt(uint32_t* f, uint32_t bbase, int nb, int k0, int l) {
    uint32_t addr = bbase + (uint32_t)((k0 + (l & 15)) * BSTRB + nb * 2);
    asm volatile("ldmatrix.sync.aligned.m8n8.x2.trans.shared.b16 {%0,%1}, [%2];"
        : "=r"(f[0]), "=r"(f[1]) : "r"(addr));
}

// ---------------------------------------------------------------------------
// Scratch (device globals)
// ---------------------------------------------------------------------------
__device__ float g_q[BB * NQ * OUTC];
__device__ float g_k[BB * NQ * OUTC];
__device__ float g_v[BB * NQ * OUTC];
__device__ uint32_t g_wh[3 * 256 * 128];
__device__ uint32_t g_wl[3 * 256 * 128];
__device__ uint32_t g_xh[1024 * 1568];
__device__ uint32_t g_xl[1024 * 1568];

// ---------------------------------------------------------------------------
// 0) Prep: weights AND fm -> bf16 hi/lo. fm threads handle 2 independent
//    coalesced items (j and j + X_HALF) -> MLP=2, latency halved.
// ---------------------------------------------------------------------------
__device__ __forceinline__ void prep_x_item(const float* __restrict__ fm, int j) {
    int row = j / 784, n4 = j % 784;
    float4 v = *(const float4*)&fm[(size_t)row * NQ + n4 * 4];
    uint32_t h0 = pk_bf2(v.y, v.x);
    uint32_t h1 = pk_bf2(v.w, v.z);
    float l0 = v.x - bf_lo_f(h0), l1 = v.y - bf_hi_f(h0);
    float l2 = v.z - bf_lo_f(h1), l3 = v.w - bf_hi_f(h1);
    size_t o = (size_t)row * 1568 + n4 * 2;
    *(uint2*)&g_xh[o] = make_uint2(h0, h1);
    *(uint2*)&g_xl[o] = make_uint2(pk_bf2(l1, l0), pk_bf2(l3, l2));
}

__global__ void prep_all(const float* __restrict__ fm, const float* __restrict__ wq,
                         const float* __restrict__ wk, const float* __restrict__ wv) {
    int idx = blockIdx.x * blockDim.x + threadIdx.x;
    if (idx < W_ITEMS) {
        int type = idx / (256 * 128);
        int rem  = idx % (256 * 128);
        const float* W = (type == 0) ? wq : (type == 1) ? wk : wv;
        float2 v = *(const float2*)&W[(size_t)rem * 2];
        uint32_t wh = pk_bf2(v.y, v.x);
        float l0 = v.x - bf_lo_f(wh), l1 = v.y - bf_hi_f(wh);
        g_wh[idx] = wh;
        g_wl[idx] = pk_bf2(l1, l0);
    } else {
        int j = idx - W_ITEMS;
        if (j >= X_HALF) return;
        // two independent items -> both LDG.128 issue before dependent work
        int j0 = j, j1 = j + X_HALF;
        int r0 = j0 / 784, c0 = j0 % 784;
        int r1 = j1 / 784, c1 = j1 % 784;
        float4 v0 = *(const float4*)&fm[(size_t)r0 * NQ + c0 * 4];
        float4 v1 = *(const float4*)&fm[(size_t)r1 * NQ + c1 * 4];
        {
            uint32_t h0 = pk_bf2(v0.y, v0.x);
            uint32_t h1 = pk_bf2(v0.w, v0.z);
            float l0 = v0.x - bf_lo_f(h0), l1 = v0.y - bf_hi_f(h0);
            float l2 = v0.z - bf_lo_f(h1), l3 = v0.w - bf_hi_f(h1);
            size_t o = (size_t)r0 * 1568 + c0 * 2;
            *(uint2*)&g_xh[o] = make_uint2(h0, h1);
            *(uint2*)&g_xl[o] = make_uint2(pk_bf2(l1, l0), pk_bf2(l3, l2));
        }
        {
            uint32_t h0 = pk_bf2(v1.y, v1.x);
            uint32_t h1 = pk_bf2(v1.w, v1.z);
            float l0 = v1.x - bf_lo_f(h0), l1 = v1.y - bf_hi_f(h0);
            float l2 = v1.z - bf_lo_f(h1), l3 = v1.w - bf_hi_f(h1);
            size_t o = (size_t)r1 * 1568 + c1 * 2;
            *(uint2*)&g_xh[o] = make_uint2(h0, h1);
            *(uint2*)&g_xl[o] = make_uint2(pk_bf2(l1, l0), pk_bf2(l3, l2));
        }
    }
}

// ---------------------------------------------------------------------------
// Fused GEMM (round-11 config, unchanged): 3xBF16 m16n8k16, all-cp.async,
// ldmatrix, 3-stage pipeline. Tile 128(o) x 64(n); 8 warps 4x2; warp 32x32.
// ---------------------------------------------------------------------------
#define A_W     (128 * STR2)
#define AH_OFF  0
#define AL_OFF  (A_W * 4)
#define BH_OFF  (2 * A_W * 4)
#define BL_OFF  (BH_OFF + 32 * BSTRB)
#define STAGE_B (BL_OFF + 32 * BSTRB)
#define NSTG    3
#define G_SMEMB (NSTG * STAGE_B)

__global__ __launch_bounds__(256, 2) void gemm_all(void) {
    extern __shared__ uint32_t smu[];
    const uint32_t sbase = smem_u32(smu);

    const int t  = threadIdx.x;
    const int id = blockIdx.x;

    const int type  = id / TPB;
    const int local = id % TPB;
    const int ni_t = local % 49;
    const int rest = local / 49;
    const int o0 = (rest & 1) * 128;
    const int b  = rest >> 1;
    const int n0 = ni_t * 64;

    float* D = ((type == 0) ? g_q : (type == 1) ? g_k : g_v) + (size_t)b * NQ * OUTC;
    const uint32_t* WHrow = g_wh + ((size_t)type * 256 + o0) * 128;
    const uint32_t* WLrow = g_wl + ((size_t)type * 256 + o0) * 128;
    const int srcrow0 = b * 512 + (type == 0 ? 256 : 0);

    const int wid = t >> 5, l = t & 31;
    const int m0w = (wid & 3) * 32;
    const int n0w = (wid >> 2) * 32;
    const int am = t >> 2, af = t & 3;
    const int brow = t >> 3, bchunk = t & 7;

    float c[2][4][4];
#pragma unroll
    for (int mi = 0; mi < 2; mi++)
#pragma unroll
        for (int ni = 0; ni < 4; ni++)
#pragma unroll
            for (int e = 0; e < 4; e++) c[mi][ni][e] = 0.f;

#define STAGE_LOAD(stb, ktile)                                                     \
    {                                                                              \
        int kw = (ktile) * 16;                                                     \
        _Pragma("unroll")                                                          \
        for (int i = 0; i < 2; i++) {                                              \
            int m = am + i * 64;                                                   \
            uint32_t doff = (uint32_t)((m * STR2 + af * 4) * 4);                   \
            cpa16((stb) + AH_OFF + doff, WHrow + (size_t)m * 128 + kw + af * 4);   \
            cpa16((stb) + AL_OFF + doff, WLrow + (size_t)m * 128 + kw + af * 4);   \
        }                                                                          \
        {                                                                          \
            size_t srcoff = ((size_t)(srcrow0 + (ktile) * KT + brow) * NQ          \
                             + n0 + bchunk * 8) * 2;                               \
            uint32_t doff = (uint32_t)(brow * BSTRB + bchunk * 16);                \
            cpa16((stb) + BH_OFF + doff, (const char*)g_xh + srcoff);              \
            cpa16((stb) + BL_OFF + doff, (const char*)g_xl + srcoff);              \
        }                                                                          \
        CPA_COMMIT();                                                              \
    }

    STAGE_LOAD(sbase, 0);
    STAGE_LOAD(sbase + STAGE_B, 1);
    CPA_WAIT1();
    __syncthreads();

#pragma unroll 1
    for (int kt = 0; kt < CIN / KT; kt++) {
        const int s = kt % NSTG;
        const uint32_t stb = sbase + (uint32_t)(s * STAGE_B);
        const uint32_t aH = stb + AH_OFF;
        const uint32_t aL = stb + AL_OFF;
        const uint32_t bH = stb + BH_OFF;
        const uint32_t bL = stb + BL_OFF;

        if (kt + 2 < CIN / KT) {
            STAGE_LOAD(sbase + (uint32_t)(((kt + 2) % NSTG) * STAGE_B), kt + 2);
        }

#pragma unroll
        for (int ks = 0; ks < 2; ks++) {
            const int kw0 = ks * 8;
            const int k0  = ks * 16;
            uint32_t ah0[4], ah1[4], al0[4], al1[4];
            ldsmA(ah0, aH, m0w,      kw0, l);
            ldsmA(ah1, aH, m0w + 16, kw0, l);
            ldsmA(al0, aL, m0w,      kw0, l);
            ldsmA(al1, aL, m0w + 16, kw0, l);
#pragma unroll
            for (int ni = 0; ni < 4; ni++) {
                uint32_t bh[2], bl[2];
                ldsmBt(bh, bH, n0w + ni * 8, k0, l);
                ldsmBt(bl, bL, n0w + ni * 8, k0, l);
                mma16(c[0][ni], ah0, bh);
                mma16(c[0][ni], ah0, bl);
                mma16(c[0][ni], al0, bh);
                mma16(c[1][ni], ah1, bh);
                mma16(c[1][ni], ah1, bl);
                mma16(c[1][ni], al1, bh);
            }
        }

        if (kt + 2 < CIN / KT) { CPA_WAIT1(); } else { CPA_WAIT0(); }
        __syncthreads();
    }

    const int r = l >> 2, q = l & 3;
    float* Ct = (float*)smu;
#pragma unroll
    for (int mi = 0; mi < 2; mi++)
#pragma unroll
        for (int ni = 0; ni < 4; ni++) {
            int m = m0w + mi * 16 + r;
            int n = n0w + ni * 8 + q * 2;
            Ct[(n)     * CSTR + m]     = c[mi][ni][0];
            Ct[(n + 1) * CSTR + m]     = c[mi][ni][1];
            Ct[(n)     * CSTR + m + 8] = c[mi][ni][2];
            Ct[(n + 1) * CSTR + m + 8] = c[mi][ni][3];
        }
    __syncthreads();
#pragma unroll
    for (int i = 0; i < 8; i++) {
        int id2 = t + i * 256;
        int n = id2 >> 5, f = id2 & 31;
        float4 v = *(float4*)&Ct[n * CSTR + f * 4];
        *(float4*)&D[(size_t)(n0 + n) * OUTC + o0 + f * 4] = v;
    }
}

// ---------------------------------------------------------------------------
// Attention (round-11 config; q-load hoisted above halo fill to overlap
// its gmem latency with the SMEM stores + barrier).
// ---------------------------------------------------------------------------
#define TPIX   14
#define NPIX   (TPIX*TPIX)
#define SSTR   197
#define ATTN_SMEM (2 * 8 * SSTR * 16 + CG * KK * 4)   // 51328 B

__global__ __launch_bounds__(128) void attn_kernel(const float* __restrict__ relh,
                                                   const float* __restrict__ relw,
                                                   float* __restrict__ out) {
    extern __shared__ float4 smbuf[];
    float4* ks   = smbuf;
    float4* vs   = smbuf + 8 * SSTR;
    float*  bias = (float*)(smbuf + 16 * SSTR);

    const int b    = blockIdx.z;
    const int g    = blockIdx.y;
    const int tile = blockIdx.x;
    const int ty0  = (tile / 7) * 8;
    const int tx0  = (tile % 7) * 8;
    const int t    = threadIdx.x;
    const int p    = t >> 1;
    const int half = t & 1;

    const int lty = p >> 3, ltx = p & 7;
    const int h = ty0 + lty, w = tx0 + ltx;
    const int pbase = lty * TPIX + ltx;
    const int c4b = half * 4;

    // hoisted q load: overlaps the halo fill + barrier below
    float qf[16];
    {
        const float4* qp = (const float4*)&g_q[((size_t)b * NQ + h * WW + w) * OUTC + g * CG];
#pragma unroll
        for (int c4 = 0; c4 < 4; c4++) {
            float4 v = qp[c4b + c4];
            qf[c4 * 4 + 0] = v.x; qf[c4 * 4 + 1] = v.y;
            qf[c4 * 4 + 2] = v.z; qf[c4 * 4 + 3] = v.w;
        }
    }

    const float* rel = (g < 4) ? (relh + (size_t)g * CG * KK)
                               : (relw + (size_t)(g - 4) * CG * KK);
    for (int i = t; i < CG * KK; i += 128) bias[i] = rel[i];

    for (int idx = t; idx < NPIX * 8; idx += 128) {
        int c4 = idx & 7;
        int pp = idx >> 3;
        int py = pp / TPIX, px = pp - py * TPIX;
        int yy = ty0 + py - PADV, xx = tx0 + px - PADV;
        float4 kv = make_float4(0.f, 0.f, 0.f, 0.f);
        float4 vv = make_float4(0.f, 0.f, 0.f, 0.f);
        if (yy >= 0 && yy < HH && xx >= 0 && xx < WW) {
            size_t gbase = ((size_t)b * NQ + yy * WW + xx) * OUTC + g * CG;
            kv = *((const float4*)&g_k[gbase] + c4);
            vv = *((const float4*)&g_v[gbase] + c4);
        }
        ks[c4 * SSTR + pp] = kv;
        vs[c4 * SSTR + pp] = vv;
    }
    __syncthreads();

    float db[KK];
#pragma unroll
    for (int i = 0; i < KK; i++) {
        float s = 0.f;
#pragma unroll
        for (int c = 0; c < 16; c++) s += qf[c] * bias[(half * 16 + c) * KK + i];
        db[i] = s;
    }
#pragma unroll
    for (int i = 0; i < KK; i++) db[i] += __shfl_xor_sync(0xffffffffu, db[i], 1);

    float lg[KK * KK];
#pragma unroll
    for (int n = 0; n < KK * KK; n++) {
        const int i = n / KK, j = n % KK;
        const int pp = pbase + i * TPIX + j;
        float s = 0.f;
#pragma unroll
        for (int c4 = 0; c4 < 4; c4++) {
            float4 kv = ks[(c4b + c4) * SSTR + pp];
            s += qf[c4 * 4 + 0] * kv.x + qf[c4 * 4 + 1] * kv.y
               + qf[c4 * 4 + 2] * kv.z + qf[c4 * 4 + 3] * kv.w;
        }
        lg[n] = s;
    }
#pragma unroll
    for (int n = 0; n < KK * KK; n++)
        lg[n] += __shfl_xor_sync(0xffffffffu, lg[n], 1);
#pragma unroll
    for (int n = 0; n < KK * KK; n++)
        lg[n] += (g < 4) ? db[n / KK] : db[n % KK];

    float mx = lg[0];
#pragma unroll
    for (int n = 1; n < KK * KK; n++) mx = fmaxf(mx, lg[n]);
    float sum = 0.f;
#pragma unroll
    for (int n = 0; n < KK * KK; n++) { lg[n] = __expf(lg[n] - mx); sum += lg[n]; }
    float inv = 1.f / sum;
#pragma unroll
    for (int n = 0; n < KK * KK; n++) lg[n] *= inv;

#pragma unroll
    for (int c4 = 0; c4 < 4; c4++) {
        float4 acc = make_float4(0.f, 0.f, 0.f, 0.f);
#pragma unroll
        for (int n = 0; n < KK * KK; n++) {
            const int pp = pbase + (n / KK) * TPIX + (n % KK);
            float4 vv = vs[(c4b + c4) * SSTR + pp];
            acc.x += lg[n] * vv.x;
            acc.y += lg[n] * vv.y;
            acc.z += lg[n] * vv.z;
            acc.w += lg[n] * vv.w;
        }
        size_t base = ((size_t)(b * OUTC + g * CG + (c4b + c4) * 4)) * NQ + h * WW + w;
        out[base]          = acc.x;
        out[base + NQ]     = acc.y;
        out[base + 2 * NQ] = acc.z;
        out[base + 3 * NQ] = acc.w;
    }
}

// ---------------------------------------------------------------------------
// Launch
// ---------------------------------------------------------------------------
extern "C" void kernel_launch(void* const* d_in, const int* in_sizes, int n_in,
                              void* d_out, int out_size) {
    const float* fm = (const float*)d_in[0];
    const float* wq = (const float*)d_in[1];
    const float* wk = (const float*)d_in[2];
    const float* wv = (const float*)d_in[3];
    const float* rh = (const float*)d_in[4];
    const float* rw = (const float*)d_in[5];
    float* out = (float*)d_out;

    cudaFuncSetAttribute(attn_kernel, cudaFuncAttributeMaxDynamicSharedMemorySize, ATTN_SMEM);
    cudaFuncSetAttribute(gemm_all,    cudaFuncAttributeMaxDynamicSharedMemorySize, G_SMEMB);

    prep_all<<<(PREP_T + 255) / 256, 256>>>(fm, wq, wk, wv);
    gemm_all<<<TOT_TILES, 256, G_SMEMB>>>();
    attn_kernel<<<dim3(49, GRP, BB), 128, ATTN_SMEM>>>(rh, rw, out);
}

// round 16
// speedup vs baseline: 1.0886x; 1.0129x over previous
#include <cuda_runtime.h>
#include <cuda_fp16.h>
#include <cstdint>

// ---------------------------------------------------------------------------
// Problem constants
// ---------------------------------------------------------------------------
#define BB    2
#define CIN   256
#define HH    56
#define WW    56
#define OUTC  256
#define KK    7
#define PADV  3
#define GRP   8
#define CG    32
#define NQ    (HH*WW)     // 3136 = 49*64

#define KT    32          // fp32 channels per k-tile
#define STR2  20          // A SMEM u32 stride per row (16 words + 4 pad)
#define BSTRB 144         // B SMEM byte stride per k-row (128B data + 16 pad)
#define CSTR  132         // epilogue transpose stride

#define TPB   196
#define TOT_TILES (3*TPB) // 588

#define W_ITEMS (3*256*128)        // weight u32 words
#define X_ITEMS (1024*784)         // fm float4 units
#define X_HALF  (X_ITEMS/2)
#define PREP_T  (W_ITEMS + X_HALF)

// ---------------------------------------------------------------------------
// helpers (portable sm_80+ PTX)
// ---------------------------------------------------------------------------
__device__ __forceinline__ void mma16(float* c, const uint32_t* a, const uint32_t* b) {
    asm volatile("mma.sync.aligned.m16n8k16.row.col.f32.bf16.bf16.f32 "
        "{%0,%1,%2,%3}, {%4,%5,%6,%7}, {%8,%9}, {%0,%1,%2,%3};"
        : "+f"(c[0]), "+f"(c[1]), "+f"(c[2]), "+f"(c[3])
        : "r"(a[0]), "r"(a[1]), "r"(a[2]), "r"(a[3]), "r"(b[0]), "r"(b[1]));
}
__device__ __forceinline__ uint32_t pk_bf2(float hi_f, float lo_f) {
    uint32_t r;
    asm("cvt.rn.bf16x2.f32 %0, %1, %2;" : "=r"(r) : "f"(hi_f), "f"(lo_f));
    return r;
}
__device__ __forceinline__ float bf_lo_f(uint32_t w) { return __uint_as_float(w << 16); }
__device__ __forceinline__ float bf_hi_f(uint32_t w) { return __uint_as_float(w & 0xFFFF0000u); }

__device__ __forceinline__ uint32_t smem_u32(const void* p) {
    return (uint32_t)__cvta_generic_to_shared(p);
}
__device__ __forceinline__ void cpa16(uint32_t dst, const void* src) {
    asm volatile("cp.async.ca.shared.global [%0], [%1], 16;" :: "r"(dst), "l"(src));
}
#define CPA_COMMIT() asm volatile("cp.async.commit_group;" ::: "memory")
#define CPA_WAIT0()  asm volatile("cp.async.wait_group 0;"  ::: "memory")
#define CPA_WAIT1()  asm volatile("cp.async.wait_group 1;"  ::: "memory")

__device__ __forceinline__ void ldsmA(uint32_t* f, uint32_t abase, int mb, int kw0, int l) {
    uint32_t addr = abase + (uint32_t)(((mb + (l & 15)) * STR2 + kw0 + ((l >> 2) & 4)) * 4);
    asm volatile("ldmatrix.sync.aligned.m8n8.x4.shared.b16 {%0,%1,%2,%3}, [%4];"
        : "=r"(f[0]), "=r"(f[1]), "=r"(f[2]), "=r"(f[3]) : "r"(addr));
}
__device__ __forceinline__ void ldsmBt(uint32_t* f, uint32_t bbase, int nb, int k0, int l) {
    uint32_t addr = bbase + (uint32_t)((k0 + (l & 15)) * BSTRB + nb * 2);
    asm volatile("ldmatrix.sync.aligned.m8n8.x2.trans.shared.b16 {%0,%1}, [%2];"
        : "=r"(f[0]), "=r"(f[1]) : "r"(addr));
}

// ---------------------------------------------------------------------------
// Scratch (device globals)
// ---------------------------------------------------------------------------
__device__ float g_q[BB * NQ * OUTC];
__device__ float g_k[BB * NQ * OUTC];
__device__ float g_v[BB * NQ * OUTC];
__device__ uint32_t g_wh[3 * 256 * 128];
__device__ uint32_t g_wl[3 * 256 * 128];
__device__ uint32_t g_xh[1024 * 1568];
__device__ uint32_t g_xl[1024 * 1568];

// ---------------------------------------------------------------------------
// 0) Prep (round-15 version)
// ---------------------------------------------------------------------------
__global__ void prep_all(const float* __restrict__ fm, const float* __restrict__ wq,
                         const float* __restrict__ wk, const float* __restrict__ wv) {
    int idx = blockIdx.x * blockDim.x + threadIdx.x;
    if (idx < W_ITEMS) {
        int type = idx / (256 * 128);
        int rem  = idx % (256 * 128);
        const float* W = (type == 0) ? wq : (type == 1) ? wk : wv;
        float2 v = *(const float2*)&W[(size_t)rem * 2];
        uint32_t wh = pk_bf2(v.y, v.x);
        float l0 = v.x - bf_lo_f(wh), l1 = v.y - bf_hi_f(wh);
        g_wh[idx] = wh;
        g_wl[idx] = pk_bf2(l1, l0);
    } else {
        int j = idx - W_ITEMS;
        if (j >= X_HALF) return;
        int j0 = j, j1 = j + X_HALF;
        int r0 = j0 / 784, c0 = j0 % 784;
        int r1 = j1 / 784, c1 = j1 % 784;
        float4 v0 = *(const float4*)&fm[(size_t)r0 * NQ + c0 * 4];
        float4 v1 = *(const float4*)&fm[(size_t)r1 * NQ + c1 * 4];
        {
            uint32_t h0 = pk_bf2(v0.y, v0.x);
            uint32_t h1 = pk_bf2(v0.w, v0.z);
            float l0 = v0.x - bf_lo_f(h0), l1 = v0.y - bf_hi_f(h0);
            float l2 = v0.z - bf_lo_f(h1), l3 = v0.w - bf_hi_f(h1);
            size_t o = (size_t)r0 * 1568 + c0 * 2;
            *(uint2*)&g_xh[o] = make_uint2(h0, h1);
            *(uint2*)&g_xl[o] = make_uint2(pk_bf2(l1, l0), pk_bf2(l3, l2));
        }
        {
            uint32_t h0 = pk_bf2(v1.y, v1.x);
            uint32_t h1 = pk_bf2(v1.w, v1.z);
            float l0 = v1.x - bf_lo_f(h0), l1 = v1.y - bf_hi_f(h0);
            float l2 = v1.z - bf_lo_f(h1), l3 = v1.w - bf_hi_f(h1);
            size_t o = (size_t)r1 * 1568 + c1 * 2;
            *(uint2*)&g_xh[o] = make_uint2(h0, h1);
            *(uint2*)&g_xl[o] = make_uint2(pk_bf2(l1, l0), pk_bf2(l3, l2));
        }
    }
}

// ---------------------------------------------------------------------------
// Fused GEMM (round-11 config, unchanged)
// ---------------------------------------------------------------------------
#define A_W     (128 * STR2)
#define AH_OFF  0
#define AL_OFF  (A_W * 4)
#define BH_OFF  (2 * A_W * 4)
#define BL_OFF  (BH_OFF + 32 * BSTRB)
#define STAGE_B (BL_OFF + 32 * BSTRB)
#define NSTG    3
#define G_SMEMB (NSTG * STAGE_B)

__global__ __launch_bounds__(256, 2) void gemm_all(void) {
    extern __shared__ uint32_t smu[];
    const uint32_t sbase = smem_u32(smu);

    const int t  = threadIdx.x;
    const int id = blockIdx.x;

    const int type  = id / TPB;
    const int local = id % TPB;
    const int ni_t = local % 49;
    const int rest = local / 49;
    const int o0 = (rest & 1) * 128;
    const int b  = rest >> 1;
    const int n0 = ni_t * 64;

    float* D = ((type == 0) ? g_q : (type == 1) ? g_k : g_v) + (size_t)b * NQ * OUTC;
    const uint32_t* WHrow = g_wh + ((size_t)type * 256 + o0) * 128;
    const uint32_t* WLrow = g_wl + ((size_t)type * 256 + o0) * 128;
    const int srcrow0 = b * 512 + (type == 0 ? 256 : 0);

    const int wid = t >> 5, l = t & 31;
    const int m0w = (wid & 3) * 32;
    const int n0w = (wid >> 2) * 32;
    const int am = t >> 2, af = t & 3;
    const int brow = t >> 3, bchunk = t & 7;

    float c[2][4][4];
#pragma unroll
    for (int mi = 0; mi < 2; mi++)
#pragma unroll
        for (int ni = 0; ni < 4; ni++)
#pragma unroll
            for (int e = 0; e < 4; e++) c[mi][ni][e] = 0.f;

#define STAGE_LOAD(stb, ktile)                                                     \
    {                                                                              \
        int kw = (ktile) * 16;                                                     \
        _Pragma("unroll")                                                          \
        for (int i = 0; i < 2; i++) {                                              \
            int m = am + i * 64;                                                   \
            uint32_t doff = (uint32_t)((m * STR2 + af * 4) * 4);                   \
            cpa16((stb) + AH_OFF + doff, WHrow + (size_t)m * 128 + kw + af * 4);   \
            cpa16((stb) + AL_OFF + doff, WLrow + (size_t)m * 128 + kw + af * 4);   \
        }                                                                          \
        {                                                                          \
            size_t srcoff = ((size_t)(srcrow0 + (ktile) * KT + brow) * NQ          \
                             + n0 + bchunk * 8) * 2;                               \
            uint32_t doff = (uint32_t)(brow * BSTRB + bchunk * 16);                \
            cpa16((stb) + BH_OFF + doff, (const char*)g_xh + srcoff);              \
            cpa16((stb) + BL_OFF + doff, (const char*)g_xl + srcoff);              \
        }                                                                          \
        CPA_COMMIT();                                                              \
    }

    STAGE_LOAD(sbase, 0);
    STAGE_LOAD(sbase + STAGE_B, 1);
    CPA_WAIT1();
    __syncthreads();

#pragma unroll 1
    for (int kt = 0; kt < CIN / KT; kt++) {
        const int s = kt % NSTG;
        const uint32_t stb = sbase + (uint32_t)(s * STAGE_B);
        const uint32_t aH = stb + AH_OFF;
        const uint32_t aL = stb + AL_OFF;
        const uint32_t bH = stb + BH_OFF;
        const uint32_t bL = stb + BL_OFF;

        if (kt + 2 < CIN / KT) {
            STAGE_LOAD(sbase + (uint32_t)(((kt + 2) % NSTG) * STAGE_B), kt + 2);
        }

#pragma unroll
        for (int ks = 0; ks < 2; ks++) {
            const int kw0 = ks * 8;
            const int k0  = ks * 16;
            uint32_t ah0[4], ah1[4], al0[4], al1[4];
            ldsmA(ah0, aH, m0w,      kw0, l);
            ldsmA(ah1, aH, m0w + 16, kw0, l);
            ldsmA(al0, aL, m0w,      kw0, l);
            ldsmA(al1, aL, m0w + 16, kw0, l);
#pragma unroll
            for (int ni = 0; ni < 4; ni++) {
                uint32_t bh[2], bl[2];
                ldsmBt(bh, bH, n0w + ni * 8, k0, l);
                ldsmBt(bl, bL, n0w + ni * 8, k0, l);
                mma16(c[0][ni], ah0, bh);
                mma16(c[0][ni], ah0, bl);
                mma16(c[0][ni], al0, bh);
                mma16(c[1][ni], ah1, bh);
                mma16(c[1][ni], ah1, bl);
                mma16(c[1][ni], al1, bh);
            }
        }

        if (kt + 2 < CIN / KT) { CPA_WAIT1(); } else { CPA_WAIT0(); }
        __syncthreads();
    }

    const int r = l >> 2, q = l & 3;
    float* Ct = (float*)smu;
#pragma unroll
    for (int mi = 0; mi < 2; mi++)
#pragma unroll
        for (int ni = 0; ni < 4; ni++) {
            int m = m0w + mi * 16 + r;
            int n = n0w + ni * 8 + q * 2;
            Ct[(n)     * CSTR + m]     = c[mi][ni][0];
            Ct[(n + 1) * CSTR + m]     = c[mi][ni][1];
            Ct[(n)     * CSTR + m + 8] = c[mi][ni][2];
            Ct[(n + 1) * CSTR + m + 8] = c[mi][ni][3];
        }
    __syncthreads();
#pragma unroll
    for (int i = 0; i < 8; i++) {
        int id2 = t + i * 256;
        int n = id2 >> 5, f = id2 & 31;
        float4 v = *(float4*)&Ct[n * CSTR + f * 4];
        *(float4*)&D[(size_t)(n0 + n) * OUTC + o0 + f * 4] = v;
    }
}

// ---------------------------------------------------------------------------
// Attention: round-15 structure (q-hoist, 2 thr/pixel), K fp32 SMEM,
// V fp16 SMEM (pass-2 crossbar bytes halved). NO register cap.
// ---------------------------------------------------------------------------
#define TPIX   14
#define NPIX   (TPIX*TPIX)
#define SSTR   197
// ks: 8*SSTR float4 (25216 B) ; vsh: 8*SSTR uint2 (12608 B) ; bias 896 B
#define ATTN_SMEM (8 * SSTR * 16 + 8 * SSTR * 8 + CG * KK * 4)   // 38720 B

__global__ __launch_bounds__(128, 4) void attn_kernel(const float* __restrict__ relh,
                                                      const float* __restrict__ relw,
                                                      float* __restrict__ out) {
    extern __shared__ float4 smbuf[];
    float4* ks   = smbuf;                              // [8][SSTR] fp32x4
    uint2*  vsh  = (uint2*)(smbuf + 8 * SSTR);         // [8][SSTR] half x4
    float*  bias = (float*)((char*)smbuf + 8 * SSTR * 16 + 8 * SSTR * 8);

    const int b    = blockIdx.z;
    const int g    = blockIdx.y;
    const int tile = blockIdx.x;
    const int ty0  = (tile / 7) * 8;
    const int tx0  = (tile % 7) * 8;
    const int t    = threadIdx.x;
    const int p    = t >> 1;
    const int half = t & 1;

    const int lty = p >> 3, ltx = p & 7;
    const int h = ty0 + lty, w = tx0 + ltx;
    const int pbase = lty * TPIX + ltx;
    const int c4b = half * 4;

    // hoisted q load (overlaps halo fill + barrier)
    float qf[16];
    {
        const float4* qp = (const float4*)&g_q[((size_t)b * NQ + h * WW + w) * OUTC + g * CG];
#pragma unroll
        for (int c4 = 0; c4 < 4; c4++) {
            float4 v = qp[c4b + c4];
            qf[c4 * 4 + 0] = v.x; qf[c4 * 4 + 1] = v.y;
            qf[c4 * 4 + 2] = v.z; qf[c4 * 4 + 3] = v.w;
        }
    }

    const float* rel = (g < 4) ? (relh + (size_t)g * CG * KK)
                               : (relw + (size_t)(g - 4) * CG * KK);
    for (int i = t; i < CG * KK; i += 128) bias[i] = rel[i];

    for (int idx = t; idx < NPIX * 8; idx += 128) {
        int c4 = idx & 7;
        int pp = idx >> 3;
        int py = pp / TPIX, px = pp - py * TPIX;
        int yy = ty0 + py - PADV, xx = tx0 + px - PADV;
        float4 kv = make_float4(0.f, 0.f, 0.f, 0.f);
        float4 vv = make_float4(0.f, 0.f, 0.f, 0.f);
        if (yy >= 0 && yy < HH && xx >= 0 && xx < WW) {
            size_t gbase = ((size_t)b * NQ + yy * WW + xx) * OUTC + g * CG;
            kv = *((const float4*)&g_k[gbase] + c4);
            vv = *((const float4*)&g_v[gbase] + c4);
        }
        ks[c4 * SSTR + pp] = kv;
        __half2 v01 = __floats2half2_rn(vv.x, vv.y);
        __half2 v23 = __floats2half2_rn(vv.z, vv.w);
        uint2 packed;
        packed.x = *(uint32_t*)&v01;
        packed.y = *(uint32_t*)&v23;
        vsh[c4 * SSTR + pp] = packed;
    }
    __syncthreads();

    float db[KK];
#pragma unroll
    for (int i = 0; i < KK; i++) {
        float s = 0.f;
#pragma unroll
        for (int c = 0; c < 16; c++) s += qf[c] * bias[(half * 16 + c) * KK + i];
        db[i] = s;
    }
#pragma unroll
    for (int i = 0; i < KK; i++) db[i] += __shfl_xor_sync(0xffffffffu, db[i], 1);

    float lg[KK * KK];
#pragma unroll
    for (int n = 0; n < KK * KK; n++) {
        const int i = n / KK, j = n % KK;
        const int pp = pbase + i * TPIX + j;
        float s = 0.f;
#pragma unroll
        for (int c4 = 0; c4 < 4; c4++) {
            float4 kv = ks[(c4b + c4) * SSTR + pp];
            s += qf[c4 * 4 + 0] * kv.x + qf[c4 * 4 + 1] * kv.y
               + qf[c4 * 4 + 2] * kv.z + qf[c4 * 4 + 3] * kv.w;
        }
        lg[n] = s;
    }
#pragma unroll
    for (int n = 0; n < KK * KK; n++)
        lg[n] += __shfl_xor_sync(0xffffffffu, lg[n], 1);
#pragma unroll
    for (int n = 0; n < KK * KK; n++)
        lg[n] += (g < 4) ? db[n / KK] : db[n % KK];

    float mx = lg[0];
#pragma unroll
    for (int n = 1; n < KK * KK; n++) mx = fmaxf(mx, lg[n]);
    float sum = 0.f;
#pragma unroll
    for (int n = 0; n < KK * KK; n++) { lg[n] = __expf(lg[n] - mx); sum += lg[n]; }
    float inv = 1.f / sum;
#pragma unroll
    for (int n = 0; n < KK * KK; n++) lg[n] *= inv;

#pragma unroll
    for (int c4 = 0; c4 < 4; c4++) {
        float4 acc = make_float4(0.f, 0.f, 0.f, 0.f);
#pragma unroll
        for (int n = 0; n < KK * KK; n++) {
            const int pp = pbase + (n / KK) * TPIX + (n % KK);
            uint2 raw = vsh[(c4b + c4) * SSTR + pp];
            float2 f01 = __half22float2(*(__half2*)&raw.x);
            float2 f23 = __half22float2(*(__half2*)&raw.y);
            acc.x += lg[n] * f01.x;
            acc.y += lg[n] * f01.y;
            acc.z += lg[n] * f23.x;
            acc.w += lg[n] * f23.y;
        }
        size_t base = ((size_t)(b * OUTC + g * CG + (c4b + c4) * 4)) * NQ + h * WW + w;
        out[base]          = acc.x;
        out[base + NQ]     = acc.y;
        out[base + 2 * NQ] = acc.z;
        out[base + 3 * NQ] = acc.w;
    }
}

// ---------------------------------------------------------------------------
// Launch
// ---------------------------------------------------------------------------
extern "C" void kernel_launch(void* const* d_in, const int* in_sizes, int n_in,
                              void* d_out, int out_size) {
    const float* fm = (const float*)d_in[0];
    const float* wq = (const float*)d_in[1];
    const float* wk = (const float*)d_in[2];
    const float* wv = (const float*)d_in[3];
    const float* rh = (const float*)d_in[4];
    const float* rw = (const float*)d_in[5];
    float* out = (float*)d_out;

    cudaFuncSetAttribute(attn_kernel, cudaFuncAttributeMaxDynamicSharedMemorySize, ATTN_SMEM);
    cudaFuncSetAttribute(gemm_all,    cudaFuncAttributeMaxDynamicSharedMemorySize, G_SMEMB);

    prep_all<<<(PREP_T + 255) / 256, 256>>>(fm, wq, wk, wv);
    gemm_all<<<TOT_TILES, 256, G_SMEMB>>>();
    attn_kernel<<<dim3(49, GRP, BB), 128, ATTN_SMEM>>>(rh, rw, out);
}